// round 5
// baseline (speedup 1.0000x reference)
#include <cuda_runtime.h>
#include <math.h>

#define N_NODES 100000
#define D 128

// Scratch (device globals: allocation-free per harness rules)
__device__ float g_sum[(size_t)N_NODES * D];   // 51.2 MB segment-sum buffer
__device__ float g_cnt[N_NODES];               // in-degree counts (float)
__device__ float g_h[(size_t)N_NODES * D];     // layer-1 activations
__device__ int   g_is64;                       // 1 if edge_index is int64

// ---------------------------------------------------------------------------
// Probe edge-index width. If int64, every odd 32-bit word is a zero high-word
// (all indices < 100000). If int32, odd words are random indices (nonzero with
// overwhelming probability across 1024 samples). Reads only the first 2048
// ints (8KB) — safe for both widths.
// ---------------------------------------------------------------------------
__global__ void detect_kernel(const int* __restrict__ ei) {
    int v = ei[2 * threadIdx.x + 1];
    int nz = __syncthreads_or(v != 0);
    if (threadIdx.x == 0) g_is64 = nz ? 0 : 1;
}

// ---------------------------------------------------------------------------
// Zero the sum buffer (and counts on the first pass)
// ---------------------------------------------------------------------------
__global__ void zero_kernel(int zero_cnt) {
    const size_t nvec = (size_t)N_NODES * D / 4;
    float4 z = make_float4(0.f, 0.f, 0.f, 0.f);
    float4* s4 = reinterpret_cast<float4*>(g_sum);
    size_t stride = (size_t)gridDim.x * blockDim.x;
    for (size_t i = (size_t)blockIdx.x * blockDim.x + threadIdx.x; i < nvec; i += stride)
        s4[i] = z;
    if (zero_cnt) {
        for (size_t i = (size_t)blockIdx.x * blockDim.x + threadIdx.x; i < N_NODES; i += stride)
            g_cnt[i] = 0.f;
    }
}

// ---------------------------------------------------------------------------
// Scatter: one warp per edge. 32 lanes x float4 = 128 floats.
// Vectorized no-return reduction (red.global.add.v4.f32) into g_sum[dst].
// Index width handled uniformly via g_is64 (low word of little-endian int64
// equals the value for indices < 2^31).
// ---------------------------------------------------------------------------
__global__ void scatter_kernel(const float* __restrict__ feat,
                               const int* __restrict__ ei,
                               int E, int add_cnt) {
    int w    = (int)((blockIdx.x * (size_t)blockDim.x + threadIdx.x) >> 5);
    int lane = threadIdx.x & 31;
    if (w >= E) return;
    int s, d;
    if (g_is64) {
        s = ei[2 * (size_t)w];
        d = ei[2 * ((size_t)E + w)];
    } else {
        s = ei[w];
        d = ei[(size_t)E + w];
    }
    float4 v = *reinterpret_cast<const float4*>(feat + (size_t)s * D + lane * 4);
    float* p = g_sum + (size_t)d * D + lane * 4;
    asm volatile("red.global.add.v4.f32 [%0], {%1,%2,%3,%4};"
                 :: "l"(p), "f"(v.x), "f"(v.y), "f"(v.z), "f"(v.w)
                 : "memory");
    if (add_cnt && lane == 0) atomicAdd(g_cnt + d, 1.0f);
}

// ---------------------------------------------------------------------------
// Fused SAGE layer: out = (sum/max(cnt,1)) @ Wl^T + b + x @ Wr^T
// optionally L2-normalized + ReLU.
// Weights transposed into SMEM (wl[k][j]); each warp computes 4 full output
// rows at once so each weight float4 load feeds 32 FMAs (smem reuse x4).
// ---------------------------------------------------------------------------
template <bool NORM_RELU>
__global__ void __launch_bounds__(512, 1)
sage_kernel(const float* __restrict__ xin,
            const float* __restrict__ Wl,
            const float* __restrict__ b,
            const float* __restrict__ Wr,
            float* __restrict__ out) {
    extern __shared__ float sm[];
    float* wl    = sm;             // [128][128] : wl[k*128 + j] = Wl[j][k]
    float* wr    = sm + 16384;     // [128][128]
    float* bs    = sm + 32768;     // [128]
    float* stage = sm + 32896;     // [16 warps][4 nodes][256]

    const int tid = threadIdx.x;

    // Transpose weights into SMEM (once per block)
    for (int i = tid; i < 16384; i += blockDim.x) {
        int k = i >> 7, j = i & 127;
        wl[i] = Wl[j * 128 + k];
        wr[i] = Wr[j * 128 + k];
    }
    if (tid < 128) bs[tid] = b[tid];
    __syncthreads();

    const int lane = tid & 31;
    const int wib  = tid >> 5;
    const int gw   = blockIdx.x * (blockDim.x >> 5) + wib;
    const int nw   = gridDim.x * (blockDim.x >> 5);
    float* st      = stage + wib * 1024;   // 4 * 256 floats per warp
    const int j0   = lane * 4;

    for (int g = gw; g < N_NODES / 4; g += nw) {
        const int base = g * 4;

        // Stage 4 nodes' inputs: [agg(128) | x(128)] each
        #pragma unroll
        for (int n = 0; n < 4; n++) {
            int node = base + n;
            float rc = 1.0f / fmaxf(g_cnt[node], 1.0f);
            float4 s4 = *reinterpret_cast<const float4*>(g_sum + (size_t)node * D + j0);
            float4 x4 = *reinterpret_cast<const float4*>(xin   + (size_t)node * D + j0);
            s4.x *= rc; s4.y *= rc; s4.z *= rc; s4.w *= rc;
            *reinterpret_cast<float4*>(st + n * 256 + j0)       = s4;
            *reinterpret_cast<float4*>(st + n * 256 + 128 + j0) = x4;
        }
        __syncwarp();

        float4 bias4 = *reinterpret_cast<const float4*>(bs + j0);
        float4 acc[4] = {bias4, bias4, bias4, bias4};

        #pragma unroll 4
        for (int k = 0; k < 128; k++) {
            float4 w1 = *reinterpret_cast<const float4*>(wl + k * 128 + j0);
            float4 w2 = *reinterpret_cast<const float4*>(wr + k * 128 + j0);
            #pragma unroll
            for (int n = 0; n < 4; n++) {
                float a  = st[n * 256 + k];         // broadcast
                float xv = st[n * 256 + 128 + k];   // broadcast
                acc[n].x = fmaf(a, w1.x, fmaf(xv, w2.x, acc[n].x));
                acc[n].y = fmaf(a, w1.y, fmaf(xv, w2.y, acc[n].y));
                acc[n].z = fmaf(a, w1.z, fmaf(xv, w2.z, acc[n].z));
                acc[n].w = fmaf(a, w1.w, fmaf(xv, w2.w, acc[n].w));
            }
        }
        __syncwarp();   // WAR protection on 'st' before next group

        #pragma unroll
        for (int n = 0; n < 4; n++) {
            float4 v = acc[n];
            if (NORM_RELU) {
                float ss = v.x * v.x + v.y * v.y + v.z * v.z + v.w * v.w;
                #pragma unroll
                for (int o = 16; o; o >>= 1) ss += __shfl_xor_sync(0xffffffffu, ss, o);
                float inv = 1.0f / fmaxf(sqrtf(ss), 1e-12f);
                v.x = fmaxf(v.x * inv, 0.f);
                v.y = fmaxf(v.y * inv, 0.f);
                v.z = fmaxf(v.z * inv, 0.f);
                v.w = fmaxf(v.w * inv, 0.f);
            }
            *reinterpret_cast<float4*>(out + (size_t)(base + n) * D + j0) = v;
        }
    }
}

// ---------------------------------------------------------------------------
extern "C" void kernel_launch(void* const* d_in, const int* in_sizes, int n_in,
                              void* d_out, int out_size) {
    const float* x   = (const float*)d_in[0];
    const int*   ei  = (const int*)d_in[1];
    const float* W1l = (const float*)d_in[2];
    const float* b1  = (const float*)d_in[3];
    const float* W1r = (const float*)d_in[4];
    const float* W2l = (const float*)d_in[5];
    const float* b2  = (const float*)d_in[6];
    const float* W2r = (const float*)d_in[7];
    float*       out = (float*)d_out;

    const int E = in_sizes[1] / 2;   // edge_index is [2, E]

    float* hbuf = nullptr;
    cudaGetSymbolAddress((void**)&hbuf, g_h);

    int sms = 148;
    cudaDeviceGetAttribute(&sms, cudaDevAttrMultiProcessorCount, 0);

    // 2x 64KB transposed weights + bias + 16 warps * 4 nodes * 256 floats staging
    const int smem_bytes = (16384 + 16384 + 128 + 16 * 1024) * (int)sizeof(float);
    cudaFuncSetAttribute(sage_kernel<true>,  cudaFuncAttributeMaxDynamicSharedMemorySize, smem_bytes);
    cudaFuncSetAttribute(sage_kernel<false>, cudaFuncAttributeMaxDynamicSharedMemorySize, smem_bytes);

    const int scatter_blocks = (E + 7) / 8;   // 8 warps (256 threads) per block

    // Probe index width once (deterministic, graph-capturable)
    detect_kernel<<<1, 1024>>>(ei);

    // ---- Layer 1 ----
    zero_kernel<<<512, 256>>>(1);
    scatter_kernel<<<scatter_blocks, 256>>>(x, ei, E, 1);
    sage_kernel<true><<<sms, 512, smem_bytes>>>(x, W1l, b1, W1r, hbuf);

    // ---- Layer 2 (counts reused) ----
    zero_kernel<<<512, 256>>>(0);
    scatter_kernel<<<scatter_blocks, 256>>>(hbuf, ei, E, 0);
    sage_kernel<false><<<sms, 512, smem_bytes>>>(hbuf, W2l, b2, W2r, out);
}

// round 6
// speedup vs baseline: 1.2020x; 1.2020x over previous
#include <cuda_runtime.h>
#include <math.h>

#define N_NODES 100000
#define D 128
#define E_MAX 2000000

// Scratch (device globals: allocation-free per harness rules)
__device__ float g_sum[(size_t)N_NODES * D];   // mean-aggregated features
__device__ float g_h[(size_t)N_NODES * D];     // layer-1 activations
__device__ int   g_off[N_NODES + 1];           // CSR row offsets (by dst)
__device__ int   g_cur[N_NODES];               // degree counts / fill cursors
__device__ int   g_src[E_MAX];                 // CSR column (src) ids
__device__ int   g_is64;                       // 1 if edge_index is int64

// ---------------------------------------------------------------------------
// Probe edge-index width: int64 indices < 100000 have zero high words.
// ---------------------------------------------------------------------------
__global__ void detect_kernel(const int* __restrict__ ei) {
    int v = ei[2 * threadIdx.x + 1];
    int nz = __syncthreads_or(v != 0);
    if (threadIdx.x == 0) g_is64 = nz ? 0 : 1;
}

__global__ void zero_deg_kernel() {
    int i = blockIdx.x * blockDim.x + threadIdx.x;
    if (i < N_NODES) g_cur[i] = 0;
}

// Degree histogram over dst
__global__ void hist_kernel(const int* __restrict__ ei, int E) {
    int i = blockIdx.x * blockDim.x + threadIdx.x;
    if (i >= E) return;
    int d = g_is64 ? ei[2 * ((size_t)E + i)] : ei[(size_t)E + i];
    atomicAdd(&g_cur[d], 1);
}

// Single-block exclusive scan of degrees -> g_off; reset g_cur to offsets.
__global__ void scan_kernel() {
    __shared__ int part[1024];
    const int tid = threadIdx.x;
    const int per = (N_NODES + 1023) / 1024;   // 98
    const int base = tid * per;

    int s = 0;
    for (int i = 0; i < per; i++) {
        int idx = base + i;
        if (idx < N_NODES) s += g_cur[idx];
    }
    part[tid] = s;
    __syncthreads();
    for (int o = 1; o < 1024; o <<= 1) {
        int v = (tid >= o) ? part[tid - o] : 0;
        __syncthreads();
        part[tid] += v;
        __syncthreads();
    }
    int run = (tid > 0) ? part[tid - 1] : 0;
    for (int i = 0; i < per; i++) {
        int idx = base + i;
        if (idx < N_NODES) {
            int deg = g_cur[idx];
            g_off[idx] = run;
            g_cur[idx] = run;   // fill cursor
            run += deg;
        }
    }
    if (tid == 1023) g_off[N_NODES] = part[1023];
}

// Scatter src ids into CSR slots
__global__ void fill_kernel(const int* __restrict__ ei, int E) {
    int i = blockIdx.x * blockDim.x + threadIdx.x;
    if (i >= E) return;
    int s, d;
    if (g_is64) {
        s = ei[2 * (size_t)i];
        d = ei[2 * ((size_t)E + i)];
    } else {
        s = ei[i];
        d = ei[(size_t)E + i];
    }
    int pos = atomicAdd(&g_cur[d], 1);
    g_src[pos] = s;
}

// ---------------------------------------------------------------------------
// Aggregation: one warp per dst node. Register accumulation (4-way unroll for
// MLP), writes the MEAN directly. No atomics, no pre-zeroing.
// ---------------------------------------------------------------------------
__global__ void __launch_bounds__(256)
agg_kernel(const float* __restrict__ feat) {
    const int w    = (int)((blockIdx.x * (size_t)blockDim.x + threadIdx.x) >> 5);
    const int lane = threadIdx.x & 31;
    if (w >= N_NODES) return;

    const int beg = g_off[w], end = g_off[w + 1];
    const int j0 = lane * 4;

    float4 a0 = make_float4(0.f, 0.f, 0.f, 0.f);
    float4 a1 = a0, a2 = a0, a3 = a0;

    int e = beg;
    for (; e + 3 < end; e += 4) {
        int s0 = g_src[e], s1 = g_src[e + 1], s2 = g_src[e + 2], s3 = g_src[e + 3];
        float4 v0 = *reinterpret_cast<const float4*>(feat + (size_t)s0 * D + j0);
        float4 v1 = *reinterpret_cast<const float4*>(feat + (size_t)s1 * D + j0);
        float4 v2 = *reinterpret_cast<const float4*>(feat + (size_t)s2 * D + j0);
        float4 v3 = *reinterpret_cast<const float4*>(feat + (size_t)s3 * D + j0);
        a0.x += v0.x; a0.y += v0.y; a0.z += v0.z; a0.w += v0.w;
        a1.x += v1.x; a1.y += v1.y; a1.z += v1.z; a1.w += v1.w;
        a2.x += v2.x; a2.y += v2.y; a2.z += v2.z; a2.w += v2.w;
        a3.x += v3.x; a3.y += v3.y; a3.z += v3.z; a3.w += v3.w;
    }
    for (; e < end; e++) {
        int s0 = g_src[e];
        float4 v0 = *reinterpret_cast<const float4*>(feat + (size_t)s0 * D + j0);
        a0.x += v0.x; a0.y += v0.y; a0.z += v0.z; a0.w += v0.w;
    }

    float rc = 1.0f / fmaxf((float)(end - beg), 1.0f);
    float4 r;
    r.x = (a0.x + a1.x + a2.x + a3.x) * rc;
    r.y = (a0.y + a1.y + a2.y + a3.y) * rc;
    r.z = (a0.z + a1.z + a2.z + a3.z) * rc;
    r.w = (a0.w + a1.w + a2.w + a3.w) * rc;
    *reinterpret_cast<float4*>(g_sum + (size_t)w * D + j0) = r;
}

// ---------------------------------------------------------------------------
// Fused SAGE layer: out = mean_agg @ Wl^T + b + x @ Wr^T (+ L2-norm + ReLU).
// Weights transposed into SMEM; each warp computes 4 full output rows so each
// weight float4 LDS feeds 32 FMAs.
// ---------------------------------------------------------------------------
template <bool NORM_RELU>
__global__ void __launch_bounds__(512, 1)
sage_kernel(const float* __restrict__ xin,
            const float* __restrict__ Wl,
            const float* __restrict__ b,
            const float* __restrict__ Wr,
            float* __restrict__ out) {
    extern __shared__ float sm[];
    float* wl    = sm;             // [128][128] : wl[k*128 + j] = Wl[j][k]
    float* wr    = sm + 16384;     // [128][128]
    float* bs    = sm + 32768;     // [128]
    float* stage = sm + 32896;     // [16 warps][4 nodes][256]

    const int tid = threadIdx.x;

    for (int i = tid; i < 16384; i += blockDim.x) {
        int k = i >> 7, j = i & 127;
        wl[i] = Wl[j * 128 + k];
        wr[i] = Wr[j * 128 + k];
    }
    if (tid < 128) bs[tid] = b[tid];
    __syncthreads();

    const int lane = tid & 31;
    const int wib  = tid >> 5;
    const int gw   = blockIdx.x * (blockDim.x >> 5) + wib;
    const int nw   = gridDim.x * (blockDim.x >> 5);
    float* st      = stage + wib * 1024;
    const int j0   = lane * 4;

    for (int g = gw; g < N_NODES / 4; g += nw) {
        const int base = g * 4;

        #pragma unroll
        for (int n = 0; n < 4; n++) {
            int node = base + n;
            float4 s4 = *reinterpret_cast<const float4*>(g_sum + (size_t)node * D + j0);
            float4 x4 = *reinterpret_cast<const float4*>(xin   + (size_t)node * D + j0);
            *reinterpret_cast<float4*>(st + n * 256 + j0)       = s4;
            *reinterpret_cast<float4*>(st + n * 256 + 128 + j0) = x4;
        }
        __syncwarp();

        float4 bias4 = *reinterpret_cast<const float4*>(bs + j0);
        float4 acc[4] = {bias4, bias4, bias4, bias4};

        #pragma unroll 4
        for (int k = 0; k < 128; k++) {
            float4 w1 = *reinterpret_cast<const float4*>(wl + k * 128 + j0);
            float4 w2 = *reinterpret_cast<const float4*>(wr + k * 128 + j0);
            #pragma unroll
            for (int n = 0; n < 4; n++) {
                float a  = st[n * 256 + k];
                float xv = st[n * 256 + 128 + k];
                acc[n].x = fmaf(a, w1.x, fmaf(xv, w2.x, acc[n].x));
                acc[n].y = fmaf(a, w1.y, fmaf(xv, w2.y, acc[n].y));
                acc[n].z = fmaf(a, w1.z, fmaf(xv, w2.z, acc[n].z));
                acc[n].w = fmaf(a, w1.w, fmaf(xv, w2.w, acc[n].w));
            }
        }
        __syncwarp();

        #pragma unroll
        for (int n = 0; n < 4; n++) {
            float4 v = acc[n];
            if (NORM_RELU) {
                float ss = v.x * v.x + v.y * v.y + v.z * v.z + v.w * v.w;
                #pragma unroll
                for (int o = 16; o; o >>= 1) ss += __shfl_xor_sync(0xffffffffu, ss, o);
                float inv = 1.0f / fmaxf(sqrtf(ss), 1e-12f);
                v.x = fmaxf(v.x * inv, 0.f);
                v.y = fmaxf(v.y * inv, 0.f);
                v.z = fmaxf(v.z * inv, 0.f);
                v.w = fmaxf(v.w * inv, 0.f);
            }
            *reinterpret_cast<float4*>(out + (size_t)(base + n) * D + j0) = v;
        }
    }
}

// ---------------------------------------------------------------------------
extern "C" void kernel_launch(void* const* d_in, const int* in_sizes, int n_in,
                              void* d_out, int out_size) {
    const float* x   = (const float*)d_in[0];
    const int*   ei  = (const int*)d_in[1];
    const float* W1l = (const float*)d_in[2];
    const float* b1  = (const float*)d_in[3];
    const float* W1r = (const float*)d_in[4];
    const float* W2l = (const float*)d_in[5];
    const float* b2  = (const float*)d_in[6];
    const float* W2r = (const float*)d_in[7];
    float*       out = (float*)d_out;

    const int E = in_sizes[1] / 2;

    float* hbuf = nullptr;
    cudaGetSymbolAddress((void**)&hbuf, g_h);

    int sms = 148;
    cudaDeviceGetAttribute(&sms, cudaDevAttrMultiProcessorCount, 0);

    const int smem_bytes = (16384 + 16384 + 128 + 16 * 1024) * (int)sizeof(float);
    cudaFuncSetAttribute(sage_kernel<true>,  cudaFuncAttributeMaxDynamicSharedMemorySize, smem_bytes);
    cudaFuncSetAttribute(sage_kernel<false>, cudaFuncAttributeMaxDynamicSharedMemorySize, smem_bytes);

    const int eb = (E + 255) / 256;
    const int ab = (N_NODES + 7) / 8;   // 8 warps per 256-thread block

    // ---- CSR build (once per launch) ----
    detect_kernel<<<1, 1024>>>(ei);
    zero_deg_kernel<<<(N_NODES + 255) / 256, 256>>>();
    hist_kernel<<<eb, 256>>>(ei, E);
    scan_kernel<<<1, 1024>>>();
    fill_kernel<<<eb, 256>>>(ei, E);

    // ---- Layer 1 ----
    agg_kernel<<<ab, 256>>>(x);
    sage_kernel<true><<<sms, 512, smem_bytes>>>(x, W1l, b1, W1r, hbuf);

    // ---- Layer 2 ----
    agg_kernel<<<ab, 256>>>(hbuf);
    sage_kernel<false><<<sms, 512, smem_bytes>>>(hbuf, W2l, b2, W2r, out);
}

// round 7
// speedup vs baseline: 1.4835x; 1.2342x over previous
#include <cuda_runtime.h>
#include <math.h>

#define N_NODES 100000
#define D 128
#define E_MAX 2000000
#define SCAN_T 1024
#define SCAN_B ((N_NODES + SCAN_T - 1) / SCAN_T)   // 98

// Scratch (device globals: allocation-free per harness rules)
__device__ float g_sum[(size_t)N_NODES * D];   // mean-aggregated features
__device__ float g_h[(size_t)N_NODES * D];     // layer-1 activations
__device__ int   g_off[N_NODES + 1];           // CSR row offsets (by dst)
__device__ int   g_cur[N_NODES];               // degree counts / fill cursors
__device__ int   g_src[E_MAX];                 // CSR column (src) ids
__device__ int   g_part[SCAN_B];               // per-block scan partials
__device__ int   g_is64;                       // 1 if edge_index is int64

// ---------------------------------------------------------------------------
// Probe edge-index width: int64 indices < 100000 have zero high words.
// ---------------------------------------------------------------------------
__global__ void detect_kernel(const int* __restrict__ ei) {
    int v = ei[2 * threadIdx.x + 1];
    int nz = __syncthreads_or(v != 0);
    if (threadIdx.x == 0) g_is64 = nz ? 0 : 1;
}

__global__ void zero_deg_kernel() {
    int i = blockIdx.x * blockDim.x + threadIdx.x;
    if (i < N_NODES) g_cur[i] = 0;
}

// Degree histogram over dst
__global__ void hist_kernel(const int* __restrict__ ei, int E) {
    int i = blockIdx.x * blockDim.x + threadIdx.x;
    if (i >= E) return;
    int d = g_is64 ? ei[2 * ((size_t)E + i)] : ei[(size_t)E + i];
    atomicAdd(&g_cur[d], 1);
}

// ---- 3-phase multi-block exclusive scan of g_cur -> g_off (+fill cursors) ----

// Phase A: per-block sums
__global__ void __launch_bounds__(SCAN_T)
scan_partial_kernel() {
    int i = blockIdx.x * SCAN_T + threadIdx.x;
    int v = (i < N_NODES) ? g_cur[i] : 0;
    int lane = threadIdx.x & 31, wid = threadIdx.x >> 5;
    #pragma unroll
    for (int o = 16; o; o >>= 1) v += __shfl_down_sync(0xffffffffu, v, o);
    __shared__ int ws[32];
    if (lane == 0) ws[wid] = v;
    __syncthreads();
    if (wid == 0) {
        int t = ws[lane];
        #pragma unroll
        for (int o = 16; o; o >>= 1) t += __shfl_down_sync(0xffffffffu, t, o);
        if (lane == 0) g_part[blockIdx.x] = t;
    }
}

// Phase B: single small block scans the 98 partials (exclusive)
__global__ void scan_part2_kernel(int E) {
    __shared__ int s[128];
    int tid = threadIdx.x;
    int v = (tid < SCAN_B) ? g_part[tid] : 0;
    s[tid] = v;
    __syncthreads();
    for (int o = 1; o < 128; o <<= 1) {
        int t = (tid >= o) ? s[tid - o] : 0;
        __syncthreads();
        s[tid] += t;
        __syncthreads();
    }
    if (tid < SCAN_B) g_part[tid] = s[tid] - v;   // exclusive prefix
    if (tid == 0) g_off[N_NODES] = E;
}

// Phase C: per-block exclusive scan + block prefix -> g_off / g_cur
__global__ void __launch_bounds__(SCAN_T)
scan_final_kernel() {
    int i = blockIdx.x * SCAN_T + threadIdx.x;
    int v = (i < N_NODES) ? g_cur[i] : 0;
    int lane = threadIdx.x & 31, wid = threadIdx.x >> 5;

    int inc = v;
    #pragma unroll
    for (int o = 1; o < 32; o <<= 1) {
        int t = __shfl_up_sync(0xffffffffu, inc, o);
        if (lane >= o) inc += t;
    }
    __shared__ int ws[32], wo[32];
    if (lane == 31) ws[wid] = inc;
    __syncthreads();
    if (wid == 0) {
        int t = ws[lane];
        int ts = t;
        #pragma unroll
        for (int o = 1; o < 32; o <<= 1) {
            int u = __shfl_up_sync(0xffffffffu, ts, o);
            if (lane >= o) ts += u;
        }
        wo[lane] = ts - t;   // exclusive warp offset
    }
    __syncthreads();
    int pre = g_part[blockIdx.x] + wo[wid] + (inc - v);
    if (i < N_NODES) { g_off[i] = pre; g_cur[i] = pre; }
}

// Scatter src ids into CSR slots
__global__ void fill_kernel(const int* __restrict__ ei, int E) {
    int i = blockIdx.x * blockDim.x + threadIdx.x;
    if (i >= E) return;
    int s, d;
    if (g_is64) {
        s = ei[2 * (size_t)i];
        d = ei[2 * ((size_t)E + i)];
    } else {
        s = ei[i];
        d = ei[(size_t)E + i];
    }
    int pos = atomicAdd(&g_cur[d], 1);
    g_src[pos] = s;
}

// ---------------------------------------------------------------------------
// Aggregation: one warp per dst node, register accumulation, writes the MEAN.
// ---------------------------------------------------------------------------
__global__ void __launch_bounds__(256)
agg_kernel(const float* __restrict__ feat) {
    const int w    = (int)((blockIdx.x * (size_t)blockDim.x + threadIdx.x) >> 5);
    const int lane = threadIdx.x & 31;
    if (w >= N_NODES) return;

    const int beg = g_off[w], end = g_off[w + 1];
    const int j0 = lane * 4;

    float4 a0 = make_float4(0.f, 0.f, 0.f, 0.f);
    float4 a1 = a0, a2 = a0, a3 = a0;

    int e = beg;
    for (; e + 3 < end; e += 4) {
        int s0 = g_src[e], s1 = g_src[e + 1], s2 = g_src[e + 2], s3 = g_src[e + 3];
        float4 v0 = *reinterpret_cast<const float4*>(feat + (size_t)s0 * D + j0);
        float4 v1 = *reinterpret_cast<const float4*>(feat + (size_t)s1 * D + j0);
        float4 v2 = *reinterpret_cast<const float4*>(feat + (size_t)s2 * D + j0);
        float4 v3 = *reinterpret_cast<const float4*>(feat + (size_t)s3 * D + j0);
        a0.x += v0.x; a0.y += v0.y; a0.z += v0.z; a0.w += v0.w;
        a1.x += v1.x; a1.y += v1.y; a1.z += v1.z; a1.w += v1.w;
        a2.x += v2.x; a2.y += v2.y; a2.z += v2.z; a2.w += v2.w;
        a3.x += v3.x; a3.y += v3.y; a3.z += v3.z; a3.w += v3.w;
    }
    for (; e < end; e++) {
        int s0 = g_src[e];
        float4 v0 = *reinterpret_cast<const float4*>(feat + (size_t)s0 * D + j0);
        a0.x += v0.x; a0.y += v0.y; a0.z += v0.z; a0.w += v0.w;
    }

    float rc = 1.0f / fmaxf((float)(end - beg), 1.0f);
    float4 r;
    r.x = (a0.x + a1.x + a2.x + a3.x) * rc;
    r.y = (a0.y + a1.y + a2.y + a3.y) * rc;
    r.z = (a0.z + a1.z + a2.z + a3.z) * rc;
    r.w = (a0.w + a1.w + a2.w + a3.w) * rc;
    *reinterpret_cast<float4*>(g_sum + (size_t)w * D + j0) = r;
}

// ---------------------------------------------------------------------------
// Fused SAGE layer: out = mean_agg @ Wl^T + b + x @ Wr^T (+ L2-norm + ReLU).
// Weights transposed into SMEM; warp computes 4 output rows; all smem reads
// are LDS.128 (weights per-lane vectors, activations float4 broadcasts).
// ---------------------------------------------------------------------------
template <bool NORM_RELU>
__global__ void __launch_bounds__(512, 1)
sage_kernel(const float* __restrict__ xin,
            const float* __restrict__ Wl,
            const float* __restrict__ b,
            const float* __restrict__ Wr,
            float* __restrict__ out) {
    extern __shared__ float sm[];
    float* wl    = sm;             // [128][128] : wl[k*128 + j] = Wl[j][k]
    float* wr    = sm + 16384;     // [128][128]
    float* bs    = sm + 32768;     // [128]
    float* stage = sm + 32896;     // [16 warps][4 nodes][256]

    const int tid = threadIdx.x;

    for (int i = tid; i < 16384; i += blockDim.x) {
        int k = i >> 7, j = i & 127;
        wl[i] = Wl[j * 128 + k];
        wr[i] = Wr[j * 128 + k];
    }
    if (tid < 128) bs[tid] = b[tid];
    __syncthreads();

    const int lane = tid & 31;
    const int wib  = tid >> 5;
    const int gw   = blockIdx.x * (blockDim.x >> 5) + wib;
    const int nw   = gridDim.x * (blockDim.x >> 5);
    float* st      = stage + wib * 1024;
    const int j0   = lane * 4;

    for (int g = gw; g < N_NODES / 4; g += nw) {
        const int base = g * 4;

        #pragma unroll
        for (int n = 0; n < 4; n++) {
            int node = base + n;
            float4 s4 = *reinterpret_cast<const float4*>(g_sum + (size_t)node * D + j0);
            float4 x4 = *reinterpret_cast<const float4*>(xin   + (size_t)node * D + j0);
            *reinterpret_cast<float4*>(st + n * 256 + j0)       = s4;
            *reinterpret_cast<float4*>(st + n * 256 + 128 + j0) = x4;
        }
        __syncwarp();

        float4 bias4 = *reinterpret_cast<const float4*>(bs + j0);
        float4 acc[4] = {bias4, bias4, bias4, bias4};

        #pragma unroll 1
        for (int k = 0; k < 128; k += 4) {
            float4 w1[4], w2[4];
            #pragma unroll
            for (int kk = 0; kk < 4; kk++) {
                w1[kk] = *reinterpret_cast<const float4*>(wl + (k + kk) * 128 + j0);
                w2[kk] = *reinterpret_cast<const float4*>(wr + (k + kk) * 128 + j0);
            }
            #pragma unroll
            for (int n = 0; n < 4; n++) {
                float4 a4 = *reinterpret_cast<const float4*>(st + n * 256 + k);       // broadcast
                float4 x4 = *reinterpret_cast<const float4*>(st + n * 256 + 128 + k); // broadcast
                acc[n].x = fmaf(a4.x, w1[0].x, fmaf(x4.x, w2[0].x, acc[n].x));
                acc[n].y = fmaf(a4.x, w1[0].y, fmaf(x4.x, w2[0].y, acc[n].y));
                acc[n].z = fmaf(a4.x, w1[0].z, fmaf(x4.x, w2[0].z, acc[n].z));
                acc[n].w = fmaf(a4.x, w1[0].w, fmaf(x4.x, w2[0].w, acc[n].w));
                acc[n].x = fmaf(a4.y, w1[1].x, fmaf(x4.y, w2[1].x, acc[n].x));
                acc[n].y = fmaf(a4.y, w1[1].y, fmaf(x4.y, w2[1].y, acc[n].y));
                acc[n].z = fmaf(a4.y, w1[1].z, fmaf(x4.y, w2[1].z, acc[n].z));
                acc[n].w = fmaf(a4.y, w1[1].w, fmaf(x4.y, w2[1].w, acc[n].w));
                acc[n].x = fmaf(a4.z, w1[2].x, fmaf(x4.z, w2[2].x, acc[n].x));
                acc[n].y = fmaf(a4.z, w1[2].y, fmaf(x4.z, w2[2].y, acc[n].y));
                acc[n].z = fmaf(a4.z, w1[2].z, fmaf(x4.z, w2[2].z, acc[n].z));
                acc[n].w = fmaf(a4.z, w1[2].w, fmaf(x4.z, w2[2].w, acc[n].w));
                acc[n].x = fmaf(a4.w, w1[3].x, fmaf(x4.w, w2[3].x, acc[n].x));
                acc[n].y = fmaf(a4.w, w1[3].y, fmaf(x4.w, w2[3].y, acc[n].y));
                acc[n].z = fmaf(a4.w, w1[3].z, fmaf(x4.w, w2[3].z, acc[n].z));
                acc[n].w = fmaf(a4.w, w1[3].w, fmaf(x4.w, w2[3].w, acc[n].w));
            }
        }
        __syncwarp();

        #pragma unroll
        for (int n = 0; n < 4; n++) {
            float4 v = acc[n];
            if (NORM_RELU) {
                float ss = v.x * v.x + v.y * v.y + v.z * v.z + v.w * v.w;
                #pragma unroll
                for (int o = 16; o; o >>= 1) ss += __shfl_xor_sync(0xffffffffu, ss, o);
                float inv = 1.0f / fmaxf(sqrtf(ss), 1e-12f);
                v.x = fmaxf(v.x * inv, 0.f);
                v.y = fmaxf(v.y * inv, 0.f);
                v.z = fmaxf(v.z * inv, 0.f);
                v.w = fmaxf(v.w * inv, 0.f);
            }
            *reinterpret_cast<float4*>(out + (size_t)(base + n) * D + j0) = v;
        }
    }
}

// ---------------------------------------------------------------------------
extern "C" void kernel_launch(void* const* d_in, const int* in_sizes, int n_in,
                              void* d_out, int out_size) {
    const float* x   = (const float*)d_in[0];
    const int*   ei  = (const int*)d_in[1];
    const float* W1l = (const float*)d_in[2];
    const float* b1  = (const float*)d_in[3];
    const float* W1r = (const float*)d_in[4];
    const float* W2l = (const float*)d_in[5];
    const float* b2  = (const float*)d_in[6];
    const float* W2r = (const float*)d_in[7];
    float*       out = (float*)d_out;

    const int E = in_sizes[1] / 2;

    float* hbuf = nullptr;
    cudaGetSymbolAddress((void**)&hbuf, g_h);

    int sms = 148;
    cudaDeviceGetAttribute(&sms, cudaDevAttrMultiProcessorCount, 0);

    const int smem_bytes = (16384 + 16384 + 128 + 16 * 1024) * (int)sizeof(float);
    cudaFuncSetAttribute(sage_kernel<true>,  cudaFuncAttributeMaxDynamicSharedMemorySize, smem_bytes);
    cudaFuncSetAttribute(sage_kernel<false>, cudaFuncAttributeMaxDynamicSharedMemorySize, smem_bytes);

    const int eb = (E + 255) / 256;
    const int ab = (N_NODES + 7) / 8;   // 8 warps per 256-thread block

    // ---- CSR build (once per launch) ----
    detect_kernel<<<1, 1024>>>(ei);
    zero_deg_kernel<<<(N_NODES + 255) / 256, 256>>>();
    hist_kernel<<<eb, 256>>>(ei, E);
    scan_partial_kernel<<<SCAN_B, SCAN_T>>>();
    scan_part2_kernel<<<1, 128>>>(E);
    scan_final_kernel<<<SCAN_B, SCAN_T>>>();
    fill_kernel<<<eb, 256>>>(ei, E);

    // ---- Layer 1 ----
    agg_kernel<<<ab, 256>>>(x);
    sage_kernel<true><<<sms, 512, smem_bytes>>>(x, W1l, b1, W1r, hbuf);

    // ---- Layer 2 ----
    agg_kernel<<<ab, 256>>>(hbuf);
    sage_kernel<false><<<sms, 512, smem_bytes>>>(hbuf, W2l, b2, W2r, out);
}

// round 8
// speedup vs baseline: 1.5960x; 1.0759x over previous
#include <cuda_runtime.h>
#include <math.h>

#define N_NODES 100000
#define D 128
#define E_MAX 2000000
#define SCAN_T 1024
#define SCAN_B ((N_NODES + SCAN_T - 1) / SCAN_T)   // 98

// Scratch (device globals: allocation-free per harness rules)
__device__ float g_sum[(size_t)N_NODES * D];   // mean-aggregated features
__device__ float g_h[(size_t)N_NODES * D];     // layer-1 activations
__device__ int   g_off[N_NODES + 1];           // CSR row offsets (by dst)
__device__ int   g_cur[N_NODES];               // degree counts / fill cursors
__device__ int   g_src[E_MAX];                 // CSR column (src) ids
__device__ int   g_part[SCAN_B];               // per-block scan partials
__device__ int   g_is64;                       // 1 if edge_index is int64

// ---- packed f32x2 helpers (sm_103a FFMA2) ----------------------------------
__device__ __forceinline__ unsigned long long pack_dup(float a) {
    unsigned long long r;
    asm("mov.b64 %0, {%1, %1};" : "=l"(r) : "f"(a));
    return r;
}
__device__ __forceinline__ void fma2(unsigned long long& d,
                                     unsigned long long a,
                                     unsigned long long b) {
    asm("fma.rn.f32x2 %0, %1, %2, %0;" : "+l"(d) : "l"(a), "l"(b));
}
__device__ __forceinline__ float2 unpack2(unsigned long long v) {
    float lo, hi;
    asm("mov.b64 {%0, %1}, %2;" : "=f"(lo), "=f"(hi) : "l"(v));
    return make_float2(lo, hi);
}

// ---------------------------------------------------------------------------
// Probe edge-index width: int64 indices < 100000 have zero high words.
// ---------------------------------------------------------------------------
__global__ void detect_kernel(const int* __restrict__ ei) {
    int v = ei[2 * threadIdx.x + 1];
    int nz = __syncthreads_or(v != 0);
    if (threadIdx.x == 0) g_is64 = nz ? 0 : 1;
}

__global__ void zero_deg_kernel() {
    int i = blockIdx.x * blockDim.x + threadIdx.x;
    if (i < N_NODES) g_cur[i] = 0;
}

// Degree histogram over dst
__global__ void hist_kernel(const int* __restrict__ ei, int E) {
    int i = blockIdx.x * blockDim.x + threadIdx.x;
    if (i >= E) return;
    int d = g_is64 ? ei[2 * ((size_t)E + i)] : ei[(size_t)E + i];
    atomicAdd(&g_cur[d], 1);
}

// ---- 3-phase multi-block exclusive scan of g_cur -> g_off (+fill cursors) ----

__global__ void __launch_bounds__(SCAN_T)
scan_partial_kernel() {
    int i = blockIdx.x * SCAN_T + threadIdx.x;
    int v = (i < N_NODES) ? g_cur[i] : 0;
    int lane = threadIdx.x & 31, wid = threadIdx.x >> 5;
    #pragma unroll
    for (int o = 16; o; o >>= 1) v += __shfl_down_sync(0xffffffffu, v, o);
    __shared__ int ws[32];
    if (lane == 0) ws[wid] = v;
    __syncthreads();
    if (wid == 0) {
        int t = ws[lane];
        #pragma unroll
        for (int o = 16; o; o >>= 1) t += __shfl_down_sync(0xffffffffu, t, o);
        if (lane == 0) g_part[blockIdx.x] = t;
    }
}

__global__ void scan_part2_kernel(int E) {
    __shared__ int s[128];
    int tid = threadIdx.x;
    int v = (tid < SCAN_B) ? g_part[tid] : 0;
    s[tid] = v;
    __syncthreads();
    for (int o = 1; o < 128; o <<= 1) {
        int t = (tid >= o) ? s[tid - o] : 0;
        __syncthreads();
        s[tid] += t;
        __syncthreads();
    }
    if (tid < SCAN_B) g_part[tid] = s[tid] - v;   // exclusive prefix
    if (tid == 0) g_off[N_NODES] = E;
}

__global__ void __launch_bounds__(SCAN_T)
scan_final_kernel() {
    int i = blockIdx.x * SCAN_T + threadIdx.x;
    int v = (i < N_NODES) ? g_cur[i] : 0;
    int lane = threadIdx.x & 31, wid = threadIdx.x >> 5;

    int inc = v;
    #pragma unroll
    for (int o = 1; o < 32; o <<= 1) {
        int t = __shfl_up_sync(0xffffffffu, inc, o);
        if (lane >= o) inc += t;
    }
    __shared__ int ws[32], wo[32];
    if (lane == 31) ws[wid] = inc;
    __syncthreads();
    if (wid == 0) {
        int t = ws[lane];
        int ts = t;
        #pragma unroll
        for (int o = 1; o < 32; o <<= 1) {
            int u = __shfl_up_sync(0xffffffffu, ts, o);
            if (lane >= o) ts += u;
        }
        wo[lane] = ts - t;
    }
    __syncthreads();
    int pre = g_part[blockIdx.x] + wo[wid] + (inc - v);
    if (i < N_NODES) { g_off[i] = pre; g_cur[i] = pre; }
}

// Scatter src ids into CSR slots
__global__ void fill_kernel(const int* __restrict__ ei, int E) {
    int i = blockIdx.x * blockDim.x + threadIdx.x;
    if (i >= E) return;
    int s, d;
    if (g_is64) {
        s = ei[2 * (size_t)i];
        d = ei[2 * ((size_t)E + i)];
    } else {
        s = ei[i];
        d = ei[(size_t)E + i];
    }
    int pos = atomicAdd(&g_cur[d], 1);
    g_src[pos] = s;
}

// ---------------------------------------------------------------------------
// Aggregation: one warp per dst node, register accumulation, writes the MEAN.
// ---------------------------------------------------------------------------
__global__ void __launch_bounds__(256)
agg_kernel(const float* __restrict__ feat) {
    const int w    = (int)((blockIdx.x * (size_t)blockDim.x + threadIdx.x) >> 5);
    const int lane = threadIdx.x & 31;
    if (w >= N_NODES) return;

    const int beg = g_off[w], end = g_off[w + 1];
    const int j0 = lane * 4;

    float4 a0 = make_float4(0.f, 0.f, 0.f, 0.f);
    float4 a1 = a0, a2 = a0, a3 = a0;

    int e = beg;
    for (; e + 3 < end; e += 4) {
        int s0 = g_src[e], s1 = g_src[e + 1], s2 = g_src[e + 2], s3 = g_src[e + 3];
        float4 v0 = *reinterpret_cast<const float4*>(feat + (size_t)s0 * D + j0);
        float4 v1 = *reinterpret_cast<const float4*>(feat + (size_t)s1 * D + j0);
        float4 v2 = *reinterpret_cast<const float4*>(feat + (size_t)s2 * D + j0);
        float4 v3 = *reinterpret_cast<const float4*>(feat + (size_t)s3 * D + j0);
        a0.x += v0.x; a0.y += v0.y; a0.z += v0.z; a0.w += v0.w;
        a1.x += v1.x; a1.y += v1.y; a1.z += v1.z; a1.w += v1.w;
        a2.x += v2.x; a2.y += v2.y; a2.z += v2.z; a2.w += v2.w;
        a3.x += v3.x; a3.y += v3.y; a3.z += v3.z; a3.w += v3.w;
    }
    for (; e < end; e++) {
        int s0 = g_src[e];
        float4 v0 = *reinterpret_cast<const float4*>(feat + (size_t)s0 * D + j0);
        a0.x += v0.x; a0.y += v0.y; a0.z += v0.z; a0.w += v0.w;
    }

    float rc = 1.0f / fmaxf((float)(end - beg), 1.0f);
    float4 r;
    r.x = (a0.x + a1.x + a2.x + a3.x) * rc;
    r.y = (a0.y + a1.y + a2.y + a3.y) * rc;
    r.z = (a0.z + a1.z + a2.z + a3.z) * rc;
    r.w = (a0.w + a1.w + a2.w + a3.w) * rc;
    *reinterpret_cast<float4*>(g_sum + (size_t)w * D + j0) = r;
}

// ---------------------------------------------------------------------------
// Fused SAGE layer with packed f32x2 (FFMA2) math:
//   out = mean_agg @ Wl^T + b + x @ Wr^T  (+ L2-norm + ReLU)
// Weights in SMEM transposed [k][j]; read as ulonglong2 so each u64 half is an
// f32x2 pair for free. Accumulators are f32x2 pairs; activation scalars are
// duplicated into (a,a) pairs with one MOV each (ALU pipe, overlaps FMA pipe).
// ---------------------------------------------------------------------------
template <bool NORM_RELU>
__global__ void __launch_bounds__(512, 1)
sage_kernel(const float* __restrict__ xin,
            const float* __restrict__ Wl,
            const float* __restrict__ b,
            const float* __restrict__ Wr,
            float* __restrict__ out) {
    extern __shared__ float sm[];
    float* wl    = sm;             // [128][128] : wl[k*128 + j] = Wl[j][k]
    float* wr    = sm + 16384;     // [128][128]
    float* bs    = sm + 32768;     // [128]
    float* stage = sm + 32896;     // [16 warps][4 nodes][256]

    const int tid = threadIdx.x;

    for (int i = tid; i < 16384; i += blockDim.x) {
        int k = i >> 7, j = i & 127;
        wl[i] = Wl[j * 128 + k];
        wr[i] = Wr[j * 128 + k];
    }
    if (tid < 128) bs[tid] = b[tid];
    __syncthreads();

    const int lane = tid & 31;
    const int wib  = tid >> 5;
    const int gw   = blockIdx.x * (blockDim.x >> 5) + wib;
    const int nw   = gridDim.x * (blockDim.x >> 5);
    float* st      = stage + wib * 1024;
    const int j0   = lane * 4;

    for (int g = gw; g < N_NODES / 4; g += nw) {
        const int base = g * 4;

        #pragma unroll
        for (int n = 0; n < 4; n++) {
            int node = base + n;
            float4 s4 = *reinterpret_cast<const float4*>(g_sum + (size_t)node * D + j0);
            float4 x4 = *reinterpret_cast<const float4*>(xin   + (size_t)node * D + j0);
            *reinterpret_cast<float4*>(st + n * 256 + j0)       = s4;
            *reinterpret_cast<float4*>(st + n * 256 + 128 + j0) = x4;
        }
        __syncwarp();

        // f32x2 accumulators: acc01 = outputs (j0, j0+1), acc23 = (j0+2, j0+3)
        const ulonglong2 bp = *reinterpret_cast<const ulonglong2*>(bs + j0);
        unsigned long long acc01[4], acc23[4];
        #pragma unroll
        for (int n = 0; n < 4; n++) { acc01[n] = bp.x; acc23[n] = bp.y; }

        #pragma unroll 1
        for (int k = 0; k < 128; k += 4) {
            ulonglong2 w1p[4], w2p[4];
            #pragma unroll
            for (int kk = 0; kk < 4; kk++) {
                w1p[kk] = *reinterpret_cast<const ulonglong2*>(wl + (k + kk) * 128 + j0);
                w2p[kk] = *reinterpret_cast<const ulonglong2*>(wr + (k + kk) * 128 + j0);
            }
            #pragma unroll
            for (int n = 0; n < 4; n++) {
                float4 a4 = *reinterpret_cast<const float4*>(st + n * 256 + k);       // broadcast
                float4 x4 = *reinterpret_cast<const float4*>(st + n * 256 + 128 + k); // broadcast
                unsigned long long p;
                p = pack_dup(a4.x); fma2(acc01[n], p, w1p[0].x); fma2(acc23[n], p, w1p[0].y);
                p = pack_dup(x4.x); fma2(acc01[n], p, w2p[0].x); fma2(acc23[n], p, w2p[0].y);
                p = pack_dup(a4.y); fma2(acc01[n], p, w1p[1].x); fma2(acc23[n], p, w1p[1].y);
                p = pack_dup(x4.y); fma2(acc01[n], p, w2p[1].x); fma2(acc23[n], p, w2p[1].y);
                p = pack_dup(a4.z); fma2(acc01[n], p, w1p[2].x); fma2(acc23[n], p, w1p[2].y);
                p = pack_dup(x4.z); fma2(acc01[n], p, w2p[2].x); fma2(acc23[n], p, w2p[2].y);
                p = pack_dup(a4.w); fma2(acc01[n], p, w1p[3].x); fma2(acc23[n], p, w1p[3].y);
                p = pack_dup(x4.w); fma2(acc01[n], p, w2p[3].x); fma2(acc23[n], p, w2p[3].y);
            }
        }
        __syncwarp();

        #pragma unroll
        for (int n = 0; n < 4; n++) {
            float2 v01 = unpack2(acc01[n]);
            float2 v23 = unpack2(acc23[n]);
            float4 v = make_float4(v01.x, v01.y, v23.x, v23.y);
            if (NORM_RELU) {
                float ss = v.x * v.x + v.y * v.y + v.z * v.z + v.w * v.w;
                #pragma unroll
                for (int o = 16; o; o >>= 1) ss += __shfl_xor_sync(0xffffffffu, ss, o);
                float inv = 1.0f / fmaxf(sqrtf(ss), 1e-12f);
                v.x = fmaxf(v.x * inv, 0.f);
                v.y = fmaxf(v.y * inv, 0.f);
                v.z = fmaxf(v.z * inv, 0.f);
                v.w = fmaxf(v.w * inv, 0.f);
            }
            *reinterpret_cast<float4*>(out + (size_t)(base + n) * D + j0) = v;
        }
    }
}

// ---------------------------------------------------------------------------
extern "C" void kernel_launch(void* const* d_in, const int* in_sizes, int n_in,
                              void* d_out, int out_size) {
    const float* x   = (const float*)d_in[0];
    const int*   ei  = (const int*)d_in[1];
    const float* W1l = (const float*)d_in[2];
    const float* b1  = (const float*)d_in[3];
    const float* W1r = (const float*)d_in[4];
    const float* W2l = (const float*)d_in[5];
    const float* b2  = (const float*)d_in[6];
    const float* W2r = (const float*)d_in[7];
    float*       out = (float*)d_out;

    const int E = in_sizes[1] / 2;

    float* hbuf = nullptr;
    cudaGetSymbolAddress((void**)&hbuf, g_h);

    int sms = 148;
    cudaDeviceGetAttribute(&sms, cudaDevAttrMultiProcessorCount, 0);

    const int smem_bytes = (16384 + 16384 + 128 + 16 * 1024) * (int)sizeof(float);
    cudaFuncSetAttribute(sage_kernel<true>,  cudaFuncAttributeMaxDynamicSharedMemorySize, smem_bytes);
    cudaFuncSetAttribute(sage_kernel<false>, cudaFuncAttributeMaxDynamicSharedMemorySize, smem_bytes);

    const int eb = (E + 255) / 256;
    const int ab = (N_NODES + 7) / 8;

    // ---- CSR build (once per launch) ----
    detect_kernel<<<1, 1024>>>(ei);
    zero_deg_kernel<<<(N_NODES + 255) / 256, 256>>>();
    hist_kernel<<<eb, 256>>>(ei, E);
    scan_partial_kernel<<<SCAN_B, SCAN_T>>>();
    scan_part2_kernel<<<1, 128>>>(E);
    scan_final_kernel<<<SCAN_B, SCAN_T>>>();
    fill_kernel<<<eb, 256>>>(ei, E);

    // ---- Layer 1 ----
    agg_kernel<<<ab, 256>>>(x);
    sage_kernel<true><<<sms, 512, smem_bytes>>>(x, W1l, b1, W1r, hbuf);

    // ---- Layer 2 ----
    agg_kernel<<<ab, 256>>>(hbuf);
    sage_kernel<false><<<sms, 512, smem_bytes>>>(hbuf, W2l, b2, W2r, out);
}

// round 9
// speedup vs baseline: 1.7977x; 1.1264x over previous
#include <cuda_runtime.h>
#include <math.h>

#define N_NODES 100000
#define D 128
#define E_MAX 2000000
#define SCAN_T 1024
#define SCAN_B ((N_NODES + SCAN_T - 1) / SCAN_T)   // 98

// Scratch (device globals: allocation-free per harness rules)
__device__ float g_sum[(size_t)N_NODES * D];   // mean-aggregated features
__device__ float g_h[(size_t)N_NODES * D];     // layer-1 activations
__device__ int   g_off[N_NODES + 1];           // CSR row offsets (by dst)
__device__ int   g_cur[N_NODES];               // degree counts / fill cursors
__device__ int   g_src[E_MAX];                 // CSR column (src) ids
__device__ int   g_part[SCAN_B];               // per-block scan partials
__device__ int   g_is64;                       // 1 if edge_index is int64

// ---- packed f32x2 helpers (sm_103a FFMA2) ----------------------------------
__device__ __forceinline__ unsigned long long pack_dup(float a) {
    unsigned long long r;
    asm("mov.b64 %0, {%1, %1};" : "=l"(r) : "f"(a));
    return r;
}
__device__ __forceinline__ void fma2(unsigned long long& d,
                                     unsigned long long a,
                                     unsigned long long b) {
    asm("fma.rn.f32x2 %0, %1, %2, %0;" : "+l"(d) : "l"(a), "l"(b));
}
__device__ __forceinline__ float2 unpack2(unsigned long long v) {
    float lo, hi;
    asm("mov.b64 {%0, %1}, %2;" : "=f"(lo), "=f"(hi) : "l"(v));
    return make_float2(lo, hi);
}

// ---------------------------------------------------------------------------
// Probe edge-index width: int64 indices < 100000 have zero high words.
// ---------------------------------------------------------------------------
__global__ void detect_kernel(const int* __restrict__ ei) {
    int v = ei[2 * threadIdx.x + 1];
    int nz = __syncthreads_or(v != 0);
    if (threadIdx.x == 0) g_is64 = nz ? 0 : 1;
}

__global__ void zero_deg_kernel() {
    int i = blockIdx.x * blockDim.x + threadIdx.x;
    if (i < N_NODES) g_cur[i] = 0;
}

__global__ void hist_kernel(const int* __restrict__ ei, int E) {
    int i = blockIdx.x * blockDim.x + threadIdx.x;
    if (i >= E) return;
    int d = g_is64 ? ei[2 * ((size_t)E + i)] : ei[(size_t)E + i];
    atomicAdd(&g_cur[d], 1);
}

// ---- 3-phase multi-block exclusive scan of g_cur -> g_off (+fill cursors) ----

__global__ void __launch_bounds__(SCAN_T)
scan_partial_kernel() {
    int i = blockIdx.x * SCAN_T + threadIdx.x;
    int v = (i < N_NODES) ? g_cur[i] : 0;
    int lane = threadIdx.x & 31, wid = threadIdx.x >> 5;
    #pragma unroll
    for (int o = 16; o; o >>= 1) v += __shfl_down_sync(0xffffffffu, v, o);
    __shared__ int ws[32];
    if (lane == 0) ws[wid] = v;
    __syncthreads();
    if (wid == 0) {
        int t = ws[lane];
        #pragma unroll
        for (int o = 16; o; o >>= 1) t += __shfl_down_sync(0xffffffffu, t, o);
        if (lane == 0) g_part[blockIdx.x] = t;
    }
}

__global__ void scan_part2_kernel(int E) {
    __shared__ int s[128];
    int tid = threadIdx.x;
    int v = (tid < SCAN_B) ? g_part[tid] : 0;
    s[tid] = v;
    __syncthreads();
    for (int o = 1; o < 128; o <<= 1) {
        int t = (tid >= o) ? s[tid - o] : 0;
        __syncthreads();
        s[tid] += t;
        __syncthreads();
    }
    if (tid < SCAN_B) g_part[tid] = s[tid] - v;   // exclusive prefix
    if (tid == 0) g_off[N_NODES] = E;
}

__global__ void __launch_bounds__(SCAN_T)
scan_final_kernel() {
    int i = blockIdx.x * SCAN_T + threadIdx.x;
    int v = (i < N_NODES) ? g_cur[i] : 0;
    int lane = threadIdx.x & 31, wid = threadIdx.x >> 5;

    int inc = v;
    #pragma unroll
    for (int o = 1; o < 32; o <<= 1) {
        int t = __shfl_up_sync(0xffffffffu, inc, o);
        if (lane >= o) inc += t;
    }
    __shared__ int ws[32], wo[32];
    if (lane == 31) ws[wid] = inc;
    __syncthreads();
    if (wid == 0) {
        int t = ws[lane];
        int ts = t;
        #pragma unroll
        for (int o = 1; o < 32; o <<= 1) {
            int u = __shfl_up_sync(0xffffffffu, ts, o);
            if (lane >= o) ts += u;
        }
        wo[lane] = ts - t;
    }
    __syncthreads();
    int pre = g_part[blockIdx.x] + wo[wid] + (inc - v);
    if (i < N_NODES) { g_off[i] = pre; g_cur[i] = pre; }
}

__global__ void fill_kernel(const int* __restrict__ ei, int E) {
    int i = blockIdx.x * blockDim.x + threadIdx.x;
    if (i >= E) return;
    int s, d;
    if (g_is64) {
        s = ei[2 * (size_t)i];
        d = ei[2 * ((size_t)E + i)];
    } else {
        s = ei[i];
        d = ei[(size_t)E + i];
    }
    int pos = atomicAdd(&g_cur[d], 1);
    g_src[pos] = s;
}

// ---------------------------------------------------------------------------
// Aggregation: one warp per dst node, register accumulation, writes the MEAN.
// ---------------------------------------------------------------------------
__global__ void __launch_bounds__(256)
agg_kernel(const float* __restrict__ feat) {
    const int w    = (int)((blockIdx.x * (size_t)blockDim.x + threadIdx.x) >> 5);
    const int lane = threadIdx.x & 31;
    if (w >= N_NODES) return;

    const int beg = g_off[w], end = g_off[w + 1];
    const int j0 = lane * 4;

    float4 a0 = make_float4(0.f, 0.f, 0.f, 0.f);
    float4 a1 = a0, a2 = a0, a3 = a0;

    int e = beg;
    for (; e + 3 < end; e += 4) {
        int s0 = g_src[e], s1 = g_src[e + 1], s2 = g_src[e + 2], s3 = g_src[e + 3];
        float4 v0 = *reinterpret_cast<const float4*>(feat + (size_t)s0 * D + j0);
        float4 v1 = *reinterpret_cast<const float4*>(feat + (size_t)s1 * D + j0);
        float4 v2 = *reinterpret_cast<const float4*>(feat + (size_t)s2 * D + j0);
        float4 v3 = *reinterpret_cast<const float4*>(feat + (size_t)s3 * D + j0);
        a0.x += v0.x; a0.y += v0.y; a0.z += v0.z; a0.w += v0.w;
        a1.x += v1.x; a1.y += v1.y; a1.z += v1.z; a1.w += v1.w;
        a2.x += v2.x; a2.y += v2.y; a2.z += v2.z; a2.w += v2.w;
        a3.x += v3.x; a3.y += v3.y; a3.z += v3.z; a3.w += v3.w;
    }
    for (; e < end; e++) {
        int s0 = g_src[e];
        float4 v0 = *reinterpret_cast<const float4*>(feat + (size_t)s0 * D + j0);
        a0.x += v0.x; a0.y += v0.y; a0.z += v0.z; a0.w += v0.w;
    }

    float rc = 1.0f / fmaxf((float)(end - beg), 1.0f);
    float4 r;
    r.x = (a0.x + a1.x + a2.x + a3.x) * rc;
    r.y = (a0.y + a1.y + a2.y + a3.y) * rc;
    r.z = (a0.z + a1.z + a2.z + a3.z) * rc;
    r.w = (a0.w + a1.w + a2.w + a3.w) * rc;
    *reinterpret_cast<float4*>(g_sum + (size_t)w * D + j0) = r;
}

// ---------------------------------------------------------------------------
// Fused SAGE layer, f32x2 FFMA2 with NODE-PAIR packing:
//   acc f32x2 lane pair = (out_j of node n0, out_j of node n1)
//   multiplier = activation pair from pair-interleaved smem (LDS broadcast,
//                no MOV), weight dup'd once per (j,k) and reused by 4 pairs.
// Warp blocks 8 nodes (4 pairs). 384 threads, 1 block/SM.
// ---------------------------------------------------------------------------
#define SAGE_T 384
#define SAGE_W (SAGE_T / 32)           // 12 warps
// smem floats: wl 16384 | wr 16384 | bias 128 | staging 12*2048
#define SAGE_SMEM_FLOATS (16384 + 16384 + 128 + SAGE_W * 2048)

template <bool NORM_RELU>
__global__ void __launch_bounds__(SAGE_T, 1)
sage_kernel(const float* __restrict__ xin,
            const float* __restrict__ Wl,
            const float* __restrict__ b,
            const float* __restrict__ Wr,
            float* __restrict__ out) {
    extern __shared__ float sm[];
    float* wl    = sm;               // [128][128] : wl[k*128+j] = Wl[j][k]
    float* wr    = sm + 16384;
    float* bs    = sm + 32768;       // [128]
    float* stage = sm + 32896;       // [12 warps][2048]

    const int tid = threadIdx.x;

    for (int i = tid; i < 16384; i += SAGE_T) {
        int k = i >> 7, j = i & 127;
        wl[i] = Wl[j * 128 + k];
        wr[i] = Wr[j * 128 + k];
    }
    for (int i = tid; i < 128; i += SAGE_T) bs[i] = b[i];
    __syncthreads();

    const int lane = tid & 31;
    const int wib  = tid >> 5;
    const int gw   = blockIdx.x * SAGE_W + wib;
    const int nw   = gridDim.x * SAGE_W;
    float* stA     = stage + wib * 2048;        // agg pairs: [4p][128k][2]
    float* stX     = stA + 1024;                // x pairs
    const int j0   = lane * 4;

    for (int g = gw; g < N_NODES / 8; g += nw) {
        const int base = g * 8;

        // ---- stage 8 nodes, pair-interleaved: st[p][2k+par] = feat_{n_par}[k]
        #pragma unroll
        for (int p = 0; p < 4; p++) {
            const int n0 = base + 2 * p, n1 = n0 + 1;
            float4 s0 = *reinterpret_cast<const float4*>(g_sum + (size_t)n0 * D + j0);
            float4 s1 = *reinterpret_cast<const float4*>(g_sum + (size_t)n1 * D + j0);
            float4 x0 = *reinterpret_cast<const float4*>(xin   + (size_t)n0 * D + j0);
            float4 x1 = *reinterpret_cast<const float4*>(xin   + (size_t)n1 * D + j0);
            float* dA = stA + p * 256 + 8 * lane;
            float* dX = stX + p * 256 + 8 * lane;
            *reinterpret_cast<float4*>(dA)     = make_float4(s0.x, s1.x, s0.y, s1.y);
            *reinterpret_cast<float4*>(dA + 4) = make_float4(s0.z, s1.z, s0.w, s1.w);
            *reinterpret_cast<float4*>(dX)     = make_float4(x0.x, x1.x, x0.y, x1.y);
            *reinterpret_cast<float4*>(dX + 4) = make_float4(x0.z, x1.z, x0.w, x1.w);
        }
        __syncwarp();

        // ---- accumulators: acc[j][p] = (out_{j0+j} of n0(p), of n1(p)), bias init
        unsigned long long acc[4][4];
        {
            float4 bv = *reinterpret_cast<const float4*>(bs + j0);
            unsigned long long b0 = pack_dup(bv.x), b1 = pack_dup(bv.y);
            unsigned long long b2 = pack_dup(bv.z), b3 = pack_dup(bv.w);
            #pragma unroll
            for (int p = 0; p < 4; p++) {
                acc[0][p] = b0; acc[1][p] = b1; acc[2][p] = b2; acc[3][p] = b3;
            }
        }

        #pragma unroll 1
        for (int k = 0; k < 128; k += 4) {
            // ---- matrix Wl with agg activations
            {
                unsigned long long wd[4][4];
                #pragma unroll
                for (int kk = 0; kk < 4; kk++) {
                    float4 wv = *reinterpret_cast<const float4*>(wl + (k + kk) * 128 + j0);
                    wd[kk][0] = pack_dup(wv.x); wd[kk][1] = pack_dup(wv.y);
                    wd[kk][2] = pack_dup(wv.z); wd[kk][3] = pack_dup(wv.w);
                }
                #pragma unroll
                for (int p = 0; p < 4; p++) {
                    ulonglong2 a01 = *reinterpret_cast<const ulonglong2*>(stA + p * 256 + 2 * k);
                    ulonglong2 a23 = *reinterpret_cast<const ulonglong2*>(stA + p * 256 + 2 * k + 4);
                    #pragma unroll
                    for (int j = 0; j < 4; j++) {
                        fma2(acc[j][p], a01.x, wd[0][j]);
                        fma2(acc[j][p], a01.y, wd[1][j]);
                        fma2(acc[j][p], a23.x, wd[2][j]);
                        fma2(acc[j][p], a23.y, wd[3][j]);
                    }
                }
            }
            // ---- matrix Wr with x activations
            {
                unsigned long long wd[4][4];
                #pragma unroll
                for (int kk = 0; kk < 4; kk++) {
                    float4 wv = *reinterpret_cast<const float4*>(wr + (k + kk) * 128 + j0);
                    wd[kk][0] = pack_dup(wv.x); wd[kk][1] = pack_dup(wv.y);
                    wd[kk][2] = pack_dup(wv.z); wd[kk][3] = pack_dup(wv.w);
                }
                #pragma unroll
                for (int p = 0; p < 4; p++) {
                    ulonglong2 a01 = *reinterpret_cast<const ulonglong2*>(stX + p * 256 + 2 * k);
                    ulonglong2 a23 = *reinterpret_cast<const ulonglong2*>(stX + p * 256 + 2 * k + 4);
                    #pragma unroll
                    for (int j = 0; j < 4; j++) {
                        fma2(acc[j][p], a01.x, wd[0][j]);
                        fma2(acc[j][p], a01.y, wd[1][j]);
                        fma2(acc[j][p], a23.x, wd[2][j]);
                        fma2(acc[j][p], a23.y, wd[3][j]);
                    }
                }
            }
        }
        __syncwarp();

        // ---- epilogue: per pair, unpack, (normalize+relu), store
        #pragma unroll
        for (int p = 0; p < 4; p++) {
            float2 v0 = unpack2(acc[0][p]);
            float2 v1 = unpack2(acc[1][p]);
            float2 v2 = unpack2(acc[2][p]);
            float2 v3 = unpack2(acc[3][p]);
            float4 o0 = make_float4(v0.x, v1.x, v2.x, v3.x);   // node base+2p
            float4 o1 = make_float4(v0.y, v1.y, v2.y, v3.y);   // node base+2p+1
            if (NORM_RELU) {
                float s0 = o0.x * o0.x + o0.y * o0.y + o0.z * o0.z + o0.w * o0.w;
                float s1 = o1.x * o1.x + o1.y * o1.y + o1.z * o1.z + o1.w * o1.w;
                #pragma unroll
                for (int o = 16; o; o >>= 1) {
                    s0 += __shfl_xor_sync(0xffffffffu, s0, o);
                    s1 += __shfl_xor_sync(0xffffffffu, s1, o);
                }
                float i0 = 1.0f / fmaxf(sqrtf(s0), 1e-12f);
                float i1 = 1.0f / fmaxf(sqrtf(s1), 1e-12f);
                o0.x = fmaxf(o0.x * i0, 0.f); o0.y = fmaxf(o0.y * i0, 0.f);
                o0.z = fmaxf(o0.z * i0, 0.f); o0.w = fmaxf(o0.w * i0, 0.f);
                o1.x = fmaxf(o1.x * i1, 0.f); o1.y = fmaxf(o1.y * i1, 0.f);
                o1.z = fmaxf(o1.z * i1, 0.f); o1.w = fmaxf(o1.w * i1, 0.f);
            }
            *reinterpret_cast<float4*>(out + (size_t)(base + 2 * p)     * D + j0) = o0;
            *reinterpret_cast<float4*>(out + (size_t)(base + 2 * p + 1) * D + j0) = o1;
        }
    }
}

// ---------------------------------------------------------------------------
extern "C" void kernel_launch(void* const* d_in, const int* in_sizes, int n_in,
                              void* d_out, int out_size) {
    const float* x   = (const float*)d_in[0];
    const int*   ei  = (const int*)d_in[1];
    const float* W1l = (const float*)d_in[2];
    const float* b1  = (const float*)d_in[3];
    const float* W1r = (const float*)d_in[4];
    const float* W2l = (const float*)d_in[5];
    const float* b2  = (const float*)d_in[6];
    const float* W2r = (const float*)d_in[7];
    float*       out = (float*)d_out;

    const int E = in_sizes[1] / 2;

    float* hbuf = nullptr;
    cudaGetSymbolAddress((void**)&hbuf, g_h);

    int sms = 148;
    cudaDeviceGetAttribute(&sms, cudaDevAttrMultiProcessorCount, 0);

    const int smem_bytes = SAGE_SMEM_FLOATS * (int)sizeof(float);   // 229,888 B
    cudaFuncSetAttribute(sage_kernel<true>,  cudaFuncAttributeMaxDynamicSharedMemorySize, smem_bytes);
    cudaFuncSetAttribute(sage_kernel<false>, cudaFuncAttributeMaxDynamicSharedMemorySize, smem_bytes);

    const int eb = (E + 255) / 256;
    const int ab = (N_NODES + 7) / 8;

    // ---- CSR build (once per launch) ----
    detect_kernel<<<1, 1024>>>(ei);
    zero_deg_kernel<<<(N_NODES + 255) / 256, 256>>>();
    hist_kernel<<<eb, 256>>>(ei, E);
    scan_partial_kernel<<<SCAN_B, SCAN_T>>>();
    scan_part2_kernel<<<1, 128>>>(E);
    scan_final_kernel<<<SCAN_B, SCAN_T>>>();
    fill_kernel<<<eb, 256>>>(ei, E);

    // ---- Layer 1 ----
    agg_kernel<<<ab, 256>>>(x);
    sage_kernel<true><<<sms, SAGE_T, smem_bytes>>>(x, W1l, b1, W1r, hbuf);

    // ---- Layer 2 ----
    agg_kernel<<<ab, 256>>>(hbuf);
    sage_kernel<false><<<sms, SAGE_T, smem_bytes>>>(hbuf, W2l, b2, W2r, out);
}